// round 1
// baseline (speedup 1.0000x reference)
#include <cuda_runtime.h>
#include <math.h>

// Problem constants
#define Bb 8
#define Ll 1024
#define Ff 1024
#define Hh 16
#define Dd 64
#define MTOT (Bb * Ll)   // 8192
#define EPS 1e-6f

// Scratch (device globals: allocation-free rule)
__device__ float g_q[MTOT * Ff];
__device__ float g_k[MTOT * Ff];
__device__ float g_v[MTOT * Ff];
__device__ float g_o[MTOT * Ff];

// ---------------------------------------------------------------------------
// SGEMM: C[M,N] = A[M,K] @ B[K,N], row-major, 128x128 block tile, BK=16,
// 256 threads, 8x8 register micro-tile per thread.
// ---------------------------------------------------------------------------
__global__ __launch_bounds__(256)
void sgemm_kernel(const float* __restrict__ A, const float* __restrict__ B,
                  float* __restrict__ C, int M, int N, int K) {
    __shared__ __align__(16) float As[16][132];  // [BK][BM+4] (transposed, padded)
    __shared__ __align__(16) float Bs[16][128];  // [BK][BN]

    const int tid = threadIdx.x;
    const int tx = tid & 15;   // 0..15 -> N dim
    const int ty = tid >> 4;   // 0..15 -> M dim

    const float* Aptr = A + (size_t)(blockIdx.y * 128) * K;
    const float* Bptr = B + blockIdx.x * 128;

    float acc[8][8];
#pragma unroll
    for (int i = 0; i < 8; i++)
#pragma unroll
        for (int j = 0; j < 8; j++) acc[i][j] = 0.f;

    for (int kt = 0; kt < K; kt += 16) {
#pragma unroll
        for (int it = 0; it < 2; it++) {
            int f = tid + it * 256;
            // A tile: 128 rows x 16 cols = 512 float4
            int row = f >> 2;
            int c4  = (f & 3) << 2;
            float4 a = *(const float4*)(Aptr + (size_t)row * K + kt + c4);
            As[c4 + 0][row] = a.x;
            As[c4 + 1][row] = a.y;
            As[c4 + 2][row] = a.z;
            As[c4 + 3][row] = a.w;
            // B tile: 16 rows x 128 cols = 512 float4
            int rowb = f >> 5;
            int col  = (f & 31) << 2;
            *(float4*)(&Bs[rowb][col]) =
                *(const float4*)(Bptr + (size_t)(kt + rowb) * N + col);
        }
        __syncthreads();

#pragma unroll
        for (int k = 0; k < 16; k++) {
            float4 a0 = *(const float4*)(&As[k][ty * 8]);
            float4 a1 = *(const float4*)(&As[k][ty * 8 + 4]);
            float4 b0 = *(const float4*)(&Bs[k][tx * 8]);
            float4 b1 = *(const float4*)(&Bs[k][tx * 8 + 4]);
            float av[8] = {a0.x, a0.y, a0.z, a0.w, a1.x, a1.y, a1.z, a1.w};
            float bv[8] = {b0.x, b0.y, b0.z, b0.w, b1.x, b1.y, b1.z, b1.w};
#pragma unroll
            for (int i = 0; i < 8; i++)
#pragma unroll
                for (int j = 0; j < 8; j++) acc[i][j] += av[i] * bv[j];
        }
        __syncthreads();
    }

    float* Cb = C + (size_t)(blockIdx.y * 128 + ty * 8) * N + blockIdx.x * 128 + tx * 8;
#pragma unroll
    for (int i = 0; i < 8; i++) {
        float4 r0 = make_float4(acc[i][0], acc[i][1], acc[i][2], acc[i][3]);
        float4 r1 = make_float4(acc[i][4], acc[i][5], acc[i][6], acc[i][7]);
        *(float4*)(Cb + (size_t)i * N)     = r0;
        *(float4*)(Cb + (size_t)i * N + 4) = r1;
    }
}

// ---------------------------------------------------------------------------
// Row LayerNorm (in-place): one block per row of 1024, 256 threads x float4.
// ---------------------------------------------------------------------------
__global__ __launch_bounds__(256)
void ln_kernel(float* __restrict__ x, const float* __restrict__ scale,
               const float* __restrict__ bias) {
    __shared__ float red[16];
    const int row = blockIdx.x;
    const int tid = threadIdx.x;
    float* xr = x + (size_t)row * Ff;

    float4 v = *(const float4*)(xr + tid * 4);
    float s  = v.x + v.y + v.z + v.w;
    float sq = v.x * v.x + v.y * v.y + v.z * v.z + v.w * v.w;
#pragma unroll
    for (int o = 16; o > 0; o >>= 1) {
        s  += __shfl_xor_sync(0xffffffffu, s, o);
        sq += __shfl_xor_sync(0xffffffffu, sq, o);
    }
    const int warp = tid >> 5, lane = tid & 31;
    if (lane == 0) { red[warp] = s; red[warp + 8] = sq; }
    __syncthreads();
    float st = 0.f, sqt = 0.f;
#pragma unroll
    for (int w = 0; w < 8; w++) { st += red[w]; sqt += red[w + 8]; }

    const float mean = st * (1.0f / Ff);
    const float var  = sqt * (1.0f / Ff) - mean * mean;
    const float inv  = rsqrtf(var + EPS);

    float4 sc = *(const float4*)(scale + tid * 4);
    float4 bi = *(const float4*)(bias + tid * 4);
    float4 out;
    out.x = (v.x - mean) * inv * sc.x + bi.x;
    out.y = (v.y - mean) * inv * sc.y + bi.y;
    out.z = (v.z - mean) * inv * sc.z + bi.z;
    out.w = (v.w - mean) * inv * sc.w + bi.w;
    *(float4*)(xr + tid * 4) = out;
}

// ---------------------------------------------------------------------------
// Flash attention: grid (L/64, B*H), 256 threads (16x16), 64x64 tiles.
// Q pre-scaled by 1/sqrt(D). Mask added (broadcast over b,h). Online softmax.
// Smem: Qs (d-major), KPs (K d-major, later reused as P r-major), Vs (c-major).
// ---------------------------------------------------------------------------
__global__ __launch_bounds__(256)
void flash_kernel(const float* __restrict__ Q, const float* __restrict__ K,
                  const float* __restrict__ V, const float* __restrict__ mask,
                  float* __restrict__ O) {
    __shared__ __align__(16) float Qs[64 * 64];   // Qs[d*64 + r]
    __shared__ __align__(16) float KPs[64 * 64];  // K: [d*64+c]; P: [r*64+c]
    __shared__ __align__(16) float Vs[64 * 64];   // Vs[c*64 + d]

    const int tid = threadIdx.x;
    const int tx = tid & 15;   // -> kv col / out dim groups of 4
    const int ty = tid >> 4;   // -> q row groups of 4
    const int q0 = blockIdx.x * 64;
    const int b  = blockIdx.y / Hh;
    const int h  = blockIdx.y % Hh;

    const float* qb = Q + (size_t)b * Ll * Ff + h * Dd;
    const float* kb = K + (size_t)b * Ll * Ff + h * Dd;
    const float* vb = V + (size_t)b * Ll * Ff + h * Dd;

    // Load Q tile transposed + scaled (1/sqrt(64) = 0.125)
    {
        int r = tid & 63, dg = tid >> 6;
#pragma unroll
        for (int s = 0; s < 4; s++) {
            int d0 = dg * 16 + s * 4;
            float4 a = *(const float4*)(qb + (size_t)(q0 + r) * Ff + d0);
            Qs[(d0 + 0) * 64 + r] = a.x * 0.125f;
            Qs[(d0 + 1) * 64 + r] = a.y * 0.125f;
            Qs[(d0 + 2) * 64 + r] = a.z * 0.125f;
            Qs[(d0 + 3) * 64 + r] = a.w * 0.125f;
        }
    }

    float o[4][4];
#pragma unroll
    for (int i = 0; i < 4; i++)
#pragma unroll
        for (int j = 0; j < 4; j++) o[i][j] = 0.f;
    float m[4] = {-1e30f, -1e30f, -1e30f, -1e30f};
    float l[4] = {0.f, 0.f, 0.f, 0.f};

    for (int k0 = 0; k0 < Ll; k0 += 64) {
        __syncthreads();  // prev iter's PV done (and Q visible on iter 0)
        // K tile (transposed to d-major) + V tile (c-major)
        {
            int c = tid & 63, dg = tid >> 6;
#pragma unroll
            for (int s = 0; s < 4; s++) {
                int d0 = dg * 16 + s * 4;
                float4 a = *(const float4*)(kb + (size_t)(k0 + c) * Ff + d0);
                KPs[(d0 + 0) * 64 + c] = a.x;
                KPs[(d0 + 1) * 64 + c] = a.y;
                KPs[(d0 + 2) * 64 + c] = a.z;
                KPs[(d0 + 3) * 64 + c] = a.w;
            }
#pragma unroll
            for (int it = 0; it < 4; it++) {
                int f = tid + it * 256;
                int cc = f >> 4, d4 = (f & 15) << 2;
                *(float4*)(&Vs[cc * 64 + d4]) =
                    *(const float4*)(vb + (size_t)(k0 + cc) * Ff + d4);
            }
        }
        __syncthreads();

        // S = Q_scaled @ K^T  (4x4 micro-tile)
        float sc[4][4];
#pragma unroll
        for (int i = 0; i < 4; i++)
#pragma unroll
            for (int j = 0; j < 4; j++) sc[i][j] = 0.f;
#pragma unroll 8
        for (int d = 0; d < 64; d++) {
            float4 a  = *(const float4*)(&Qs[d * 64 + ty * 4]);
            float4 bq = *(const float4*)(&KPs[d * 64 + tx * 4]);
            float av[4]  = {a.x, a.y, a.z, a.w};
            float bvv[4] = {bq.x, bq.y, bq.z, bq.w};
#pragma unroll
            for (int i = 0; i < 4; i++)
#pragma unroll
                for (int j = 0; j < 4; j++) sc[i][j] += av[i] * bvv[j];
        }

        // mask + online softmax (row reductions over 16 tx lanes via shfl)
#pragma unroll
        for (int i = 0; i < 4; i++) {
            float4 mv = *(const float4*)(mask + (size_t)(q0 + ty * 4 + i) * Ll + k0 + tx * 4);
            sc[i][0] += mv.x; sc[i][1] += mv.y; sc[i][2] += mv.z; sc[i][3] += mv.w;

            float mx = fmaxf(fmaxf(sc[i][0], sc[i][1]), fmaxf(sc[i][2], sc[i][3]));
#pragma unroll
            for (int off = 1; off < 16; off <<= 1)
                mx = fmaxf(mx, __shfl_xor_sync(0xffffffffu, mx, off));
            float newm = fmaxf(m[i], mx);
            float fac  = __expf(m[i] - newm);
            float sum  = 0.f;
#pragma unroll
            for (int j = 0; j < 4; j++) {
                float p = __expf(sc[i][j] - newm);
                sc[i][j] = p;
                sum += p;
            }
#pragma unroll
            for (int off = 1; off < 16; off <<= 1)
                sum += __shfl_xor_sync(0xffffffffu, sum, off);
            l[i] = l[i] * fac + sum;
            m[i] = newm;
#pragma unroll
            for (int j = 0; j < 4; j++) o[i][j] *= fac;
        }
        __syncthreads();  // everyone done reading KPs as K

        // Write P over KPs, r-major
#pragma unroll
        for (int i = 0; i < 4; i++) {
            float4 pv = make_float4(sc[i][0], sc[i][1], sc[i][2], sc[i][3]);
            *(float4*)(&KPs[(ty * 4 + i) * 64 + tx * 4]) = pv;
        }
        __syncthreads();

        // O += P @ V
#pragma unroll 4
        for (int c = 0; c < 64; c++) {
            float4 bv4 = *(const float4*)(&Vs[c * 64 + tx * 4]);
            float bvv[4] = {bv4.x, bv4.y, bv4.z, bv4.w};
#pragma unroll
            for (int i = 0; i < 4; i++) {
                float a = KPs[(ty * 4 + i) * 64 + c];
#pragma unroll
                for (int j = 0; j < 4; j++) o[i][j] += a * bvv[j];
            }
        }
    }

    // Normalize and write: O[b, q0+r, h*64 + d]
    float* ob = O + (size_t)b * Ll * Ff + h * Dd;
#pragma unroll
    for (int i = 0; i < 4; i++) {
        float inv = 1.0f / l[i];
        float4 r4 = make_float4(o[i][0] * inv, o[i][1] * inv,
                                o[i][2] * inv, o[i][3] * inv);
        *(float4*)(ob + (size_t)(q0 + ty * 4 + i) * Ff + tx * 4) = r4;
    }
}

// ---------------------------------------------------------------------------
// Launch
// ---------------------------------------------------------------------------
extern "C" void kernel_launch(void* const* d_in, const int* in_sizes, int n_in,
                              void* d_out, int out_size) {
    const float* kv    = (const float*)d_in[0];
    const float* q     = (const float*)d_in[1];
    const float* mask  = (const float*)d_in[2];
    const float* Wq    = (const float*)d_in[3];
    const float* Wk    = (const float*)d_in[4];
    const float* Wv    = (const float*)d_in[5];
    const float* Wo    = (const float*)d_in[6];
    const float* lnq_s = (const float*)d_in[7];
    const float* lnq_b = (const float*)d_in[8];
    const float* lnk_s = (const float*)d_in[9];
    const float* lnk_b = (const float*)d_in[10];
    const float* lnv_s = (const float*)d_in[11];
    const float* lnv_b = (const float*)d_in[12];
    float* out = (float*)d_out;

    float *pq, *pk, *pv, *po;
    cudaGetSymbolAddress((void**)&pq, g_q);
    cudaGetSymbolAddress((void**)&pk, g_k);
    cudaGetSymbolAddress((void**)&pv, g_v);
    cudaGetSymbolAddress((void**)&po, g_o);

    dim3 gemm_grid(Ff / 128, MTOT / 128);  // (8, 64)

    sgemm_kernel<<<gemm_grid, 256>>>(q,  Wq, pq, MTOT, Ff, Ff);
    sgemm_kernel<<<gemm_grid, 256>>>(kv, Wk, pk, MTOT, Ff, Ff);
    sgemm_kernel<<<gemm_grid, 256>>>(kv, Wv, pv, MTOT, Ff, Ff);

    ln_kernel<<<MTOT, 256>>>(pq, lnq_s, lnq_b);
    ln_kernel<<<MTOT, 256>>>(pk, lnk_s, lnk_b);
    ln_kernel<<<MTOT, 256>>>(pv, lnv_s, lnv_b);

    flash_kernel<<<dim3(Ll / 64, Bb * Hh), 256>>>(pq, pk, pv, mask, po);

    sgemm_kernel<<<gemm_grid, 256>>>(po, Wo, out, MTOT, Ff, Ff);
}

// round 3
// speedup vs baseline: 1.5601x; 1.5601x over previous
#include <cuda_runtime.h>
#include <cuda_fp16.h>
#include <cstdint>
#include <math.h>

// Problem constants
#define Bb 8
#define Ll 1024
#define Ff 1024
#define Hh 16
#define Dd 64
#define MTOT (Bb * Ll)   // 8192
#define EPS 1e-6f

// ---------------------------------------------------------------------------
// Scratch (device globals: allocation-free rule)
// ---------------------------------------------------------------------------
__device__ float g_q[MTOT * Ff];
__device__ float g_k[MTOT * Ff];
__device__ float g_v[MTOT * Ff];
__device__ __half g_qh[MTOT * Ff];
__device__ __half g_ql[MTOT * Ff];
__device__ __half g_kvh[MTOT * Ff];
__device__ __half g_kvl[MTOT * Ff];
__device__ __half g_oh[MTOT * Ff];
__device__ __half g_ol[MTOT * Ff];
__device__ __half g_wh[4][Ff * Ff];   // W^T hi  [N][K]
__device__ __half g_wl[4][Ff * Ff];   // W^T lo  [N][K]

// ---------------------------------------------------------------------------
// PTX helpers (all sm_80+ portable: NO tcgen05 / no arch-"a" features)
// ---------------------------------------------------------------------------
__device__ __forceinline__ uint32_t smem_u32(const void* p) {
    uint32_t a;
    asm("{ .reg .u64 t; cvta.to.shared.u64 t, %1; cvt.u32.u64 %0, t; }"
        : "=r"(a) : "l"(p));
    return a;
}

__device__ __forceinline__ void ldsm4(uint32_t* r, uint32_t addr) {
    asm volatile("ldmatrix.sync.aligned.m8n8.x4.shared.b16 {%0,%1,%2,%3}, [%4];"
                 : "=r"(r[0]), "=r"(r[1]), "=r"(r[2]), "=r"(r[3]) : "r"(addr));
}

__device__ __forceinline__ void mma16816(float* c, const uint32_t* a, const uint32_t* b) {
    asm volatile(
        "mma.sync.aligned.m16n8k16.row.col.f32.f16.f16.f32 "
        "{%0,%1,%2,%3}, {%4,%5,%6,%7}, {%8,%9}, {%0,%1,%2,%3};"
        : "+f"(c[0]), "+f"(c[1]), "+f"(c[2]), "+f"(c[3])
        : "r"(a[0]), "r"(a[1]), "r"(a[2]), "r"(a[3]), "r"(b[0]), "r"(b[1]));
}

#define CP_ASYNC16(dst, src) \
    asm volatile("cp.async.cg.shared.global [%0], [%1], 16;" :: "r"(dst), "l"(src) : "memory")
#define CP_COMMIT() asm volatile("cp.async.commit_group;" ::: "memory")
#define CP_WAIT1()  asm volatile("cp.async.wait_group 1;" ::: "memory")

__device__ __forceinline__ void split1(float v, __half& h, __half& l) {
    h = __float2half(v);
    l = __float2half(v - __half2float(h));
}

// ---------------------------------------------------------------------------
// fp32 -> (hi, lo) fp16 split, elementwise.
// ---------------------------------------------------------------------------
__global__ __launch_bounds__(256)
void convert_split(const float* __restrict__ X, __half* __restrict__ H,
                   __half* __restrict__ L) {
    int i = blockIdx.x * 256 + threadIdx.x;
    float4 v = ((const float4*)X)[i];
    __half h0, h1, h2, h3, l0, l1, l2, l3;
    split1(v.x, h0, l0); split1(v.y, h1, l1);
    split1(v.z, h2, l2); split1(v.w, h3, l3);
    __half2 ha = __halves2half2(h0, h1), hb = __halves2half2(h2, h3);
    __half2 la = __halves2half2(l0, l1), lb = __halves2half2(l2, l3);
    uint2 hu, lu;
    hu.x = *(uint32_t*)&ha; hu.y = *(uint32_t*)&hb;
    lu.x = *(uint32_t*)&la; lu.y = *(uint32_t*)&lb;
    ((uint2*)H)[i] = hu;
    ((uint2*)L)[i] = lu;
}

// ---------------------------------------------------------------------------
// Transpose + split all 4 weight matrices: Wt[n][k] = W[k][n] as hi/lo fp16.
// grid (32, 32, 4), block (32, 8).
// ---------------------------------------------------------------------------
__global__ __launch_bounds__(256)
void transpose_split_all(const float* __restrict__ Wq, const float* __restrict__ Wk,
                         const float* __restrict__ Wv, const float* __restrict__ Wo) {
    __shared__ float t[32][33];
    const float* W;
    switch (blockIdx.z) {
        case 0: W = Wq; break;
        case 1: W = Wk; break;
        case 2: W = Wv; break;
        default: W = Wo; break;
    }
    __half* H = g_wh[blockIdx.z];
    __half* L = g_wl[blockIdx.z];

    const int tx = threadIdx.x, ty = threadIdx.y;
    const int x0 = blockIdx.x * 32;  // n
    const int y0 = blockIdx.y * 32;  // k
#pragma unroll
    for (int j = ty; j < 32; j += 8)
        t[j][tx] = W[(size_t)(y0 + j) * Ff + x0 + tx];
    __syncthreads();
#pragma unroll
    for (int j = ty; j < 32; j += 8) {
        float v = t[tx][j];  // = W[y0+tx][x0+j]
        __half h, l;
        split1(v, h, l);
        size_t idx = (size_t)(x0 + j) * Ff + y0 + tx;
        H[idx] = h;
        L[idx] = l;
    }
}

// ---------------------------------------------------------------------------
// mma.sync fp16 split-precision GEMM:
//   C[8192,1024](fp32) = (Ah+Al) @ (Bh+Bl)^T   (3 products: AhBh + AhBl + AlBh)
// A: [M][K] hi/lo fp16. B: [N][K] hi/lo fp16 (K contiguous).
// CTA tile 128x128, BK=32, 2-stage cp.async pipeline, 8 warps (64x32 each).
// Smem rows padded to 40 halves (80B) -> conflict-free ldmatrix.
// ---------------------------------------------------------------------------
#define ROWST 40
#define MATST (128 * ROWST)          // 5120 halves per matrix tile
#define STAGEST (4 * MATST)          // 20480 halves per stage
#define GEMM_SMEM_BYTES (2 * STAGEST * 2)  // 81920 B

__device__ __forceinline__ void gemm_issue(
    const __half* __restrict__ Ah, const __half* __restrict__ Al,
    const __half* __restrict__ Bh, const __half* __restrict__ Bl,
    int m0, int n0, int kc, uint32_t sstage, int tid) {
    const int k0 = kc * 32;
    const int row = tid >> 2;
    const int ch  = tid & 3;
    const __half* srcs[4] = {Ah, Al, Bh, Bl};
#pragma unroll
    for (int j = 0; j < 8; j++) {
        const int mat = j >> 1;
        const int r = row + ((j & 1) << 6);       // 0..127
        const int gr = ((mat < 2) ? m0 : n0) + r;
        const __half* src = srcs[mat] + (size_t)gr * Ff + k0 + ch * 8;
        uint32_t dst = sstage + (uint32_t)(mat * MATST + r * ROWST + ch * 8) * 2;
        CP_ASYNC16(dst, src);
    }
}

__global__ __launch_bounds__(256)
void gemm_mma(const __half* __restrict__ Ah, const __half* __restrict__ Al,
              const __half* __restrict__ Bh, const __half* __restrict__ Bl,
              float* __restrict__ C) {
    extern __shared__ __align__(16) __half sm[];
    const int tid = threadIdx.x;
    const int lane = tid & 31;
    const int wid = tid >> 5;
    const int wm = (wid >> 2) * 64;   // 0 or 64
    const int wn = (wid & 3) * 32;    // 0,32,64,96
    const int m0 = blockIdx.y * 128;
    const int n0 = blockIdx.x * 128;
    const uint32_t sbase = smem_u32(sm);

    float acc[4][4][4];
#pragma unroll
    for (int i = 0; i < 4; i++)
#pragma unroll
        for (int j = 0; j < 4; j++)
#pragma unroll
            for (int r = 0; r < 4; r++) acc[i][j][r] = 0.f;

    gemm_issue(Ah, Al, Bh, Bl, m0, n0, 0, sbase, tid);
    CP_COMMIT();
    gemm_issue(Ah, Al, Bh, Bl, m0, n0, 1, sbase + STAGEST * 2, tid);
    CP_COMMIT();

    // ldmatrix lane address components (constant across iters)
    const int a_row = (lane & 15);
    const int a_col = (lane >> 4) << 3;
    const int bq = lane >> 3;
    const int b_row = (lane & 7) + ((bq >> 1) << 3);
    const int b_col = (bq & 1) << 3;

    for (int kc = 0; kc < 32; kc++) {
        CP_WAIT1();
        __syncthreads();
        const uint32_t st = sbase + (uint32_t)((kc & 1) * STAGEST) * 2;
        const uint32_t sAh = st;
        const uint32_t sAl = st + MATST * 2;
        const uint32_t sBh = st + 2 * MATST * 2;
        const uint32_t sBl = st + 3 * MATST * 2;

#pragma unroll
        for (int kk = 0; kk < 2; kk++) {
            uint32_t ah[4][4], al[4][4], bh[4][2], bl[4][2];
#pragma unroll
            for (int mi = 0; mi < 4; mi++) {
                uint32_t off = (uint32_t)((wm + mi * 16 + a_row) * ROWST + kk * 16 + a_col) * 2;
                ldsm4(ah[mi], sAh + off);
                ldsm4(al[mi], sAl + off);
            }
#pragma unroll
            for (int g = 0; g < 2; g++) {
                uint32_t off = (uint32_t)((wn + g * 16 + b_row) * ROWST + kk * 16 + b_col) * 2;
                uint32_t r[4];
                ldsm4(r, sBh + off);
                bh[g * 2][0] = r[0]; bh[g * 2][1] = r[1];
                bh[g * 2 + 1][0] = r[2]; bh[g * 2 + 1][1] = r[3];
                ldsm4(r, sBl + off);
                bl[g * 2][0] = r[0]; bl[g * 2][1] = r[1];
                bl[g * 2 + 1][0] = r[2]; bl[g * 2 + 1][1] = r[3];
            }
#pragma unroll
            for (int mi = 0; mi < 4; mi++)
#pragma unroll
                for (int ni = 0; ni < 4; ni++) {
                    mma16816(acc[mi][ni], ah[mi], bh[ni]);
                    mma16816(acc[mi][ni], ah[mi], bl[ni]);
                    mma16816(acc[mi][ni], al[mi], bh[ni]);
                }
        }
        __syncthreads();
        if (kc + 2 < 32)
            gemm_issue(Ah, Al, Bh, Bl, m0, n0, kc + 2,
                       sbase + (uint32_t)((kc & 1) * STAGEST) * 2, tid);
        CP_COMMIT();
    }

    // Epilogue: fp32 C
    const int er = lane >> 2;
    const int ec = (lane & 3) * 2;
#pragma unroll
    for (int mi = 0; mi < 4; mi++) {
        const int r0 = m0 + wm + mi * 16 + er;
#pragma unroll
        for (int ni = 0; ni < 4; ni++) {
            const int c = n0 + wn + ni * 8 + ec;
            *(float2*)(C + (size_t)r0 * Ff + c) = make_float2(acc[mi][ni][0], acc[mi][ni][1]);
            *(float2*)(C + (size_t)(r0 + 8) * Ff + c) = make_float2(acc[mi][ni][2], acc[mi][ni][3]);
        }
    }
}

// ---------------------------------------------------------------------------
// Row LayerNorm (in-place): one block per row of 1024, 256 threads x float4.
// ---------------------------------------------------------------------------
__global__ __launch_bounds__(256)
void ln_kernel(float* __restrict__ x, const float* __restrict__ scale,
               const float* __restrict__ bias) {
    __shared__ float red[16];
    const int row = blockIdx.x;
    const int tid = threadIdx.x;
    float* xr = x + (size_t)row * Ff;

    float4 v = *(const float4*)(xr + tid * 4);
    float s  = v.x + v.y + v.z + v.w;
    float sq = v.x * v.x + v.y * v.y + v.z * v.z + v.w * v.w;
#pragma unroll
    for (int o = 16; o > 0; o >>= 1) {
        s  += __shfl_xor_sync(0xffffffffu, s, o);
        sq += __shfl_xor_sync(0xffffffffu, sq, o);
    }
    const int warp = tid >> 5, lane = tid & 31;
    if (lane == 0) { red[warp] = s; red[warp + 8] = sq; }
    __syncthreads();
    float st = 0.f, sqt = 0.f;
#pragma unroll
    for (int w = 0; w < 8; w++) { st += red[w]; sqt += red[w + 8]; }

    const float mean = st * (1.0f / Ff);
    const float var  = sqt * (1.0f / Ff) - mean * mean;
    const float inv  = rsqrtf(var + EPS);

    float4 sc = *(const float4*)(scale + tid * 4);
    float4 bi = *(const float4*)(bias + tid * 4);
    float4 out;
    out.x = (v.x - mean) * inv * sc.x + bi.x;
    out.y = (v.y - mean) * inv * sc.y + bi.y;
    out.z = (v.z - mean) * inv * sc.z + bi.z;
    out.w = (v.w - mean) * inv * sc.w + bi.w;
    *(float4*)(xr + tid * 4) = out;
}

// ---------------------------------------------------------------------------
// Flash attention (fp32): grid (L/64, B*H), 256 threads (16x16), 64x64 tiles.
// Writes output directly as (hi, lo) fp16 split for the final GEMM.
// ---------------------------------------------------------------------------
__global__ __launch_bounds__(256)
void flash_kernel(const float* __restrict__ Q, const float* __restrict__ K,
                  const float* __restrict__ V, const float* __restrict__ mask,
                  __half* __restrict__ Oh, __half* __restrict__ Ol) {
    __shared__ __align__(16) float Qs[64 * 64];   // Qs[d*64 + r]
    __shared__ __align__(16) float KPs[64 * 64];  // K: [d*64+c]; P: [r*64+c]
    __shared__ __align__(16) float Vs[64 * 64];   // Vs[c*64 + d]

    const int tid = threadIdx.x;
    const int tx = tid & 15;
    const int ty = tid >> 4;
    const int q0 = blockIdx.x * 64;
    const int b  = blockIdx.y / Hh;
    const int h  = blockIdx.y % Hh;

    const float* qb = Q + (size_t)b * Ll * Ff + h * Dd;
    const float* kb = K + (size_t)b * Ll * Ff + h * Dd;
    const float* vb = V + (size_t)b * Ll * Ff + h * Dd;

    {
        int r = tid & 63, dg = tid >> 6;
#pragma unroll
        for (int s = 0; s < 4; s++) {
            int d0 = dg * 16 + s * 4;
            float4 a = *(const float4*)(qb + (size_t)(q0 + r) * Ff + d0);
            Qs[(d0 + 0) * 64 + r] = a.x * 0.125f;
            Qs[(d0 + 1) * 64 + r] = a.y * 0.125f;
            Qs[(d0 + 2) * 64 + r] = a.z * 0.125f;
            Qs[(d0 + 3) * 64 + r] = a.w * 0.125f;
        }
    }

    float o[4][4];
#pragma unroll
    for (int i = 0; i < 4; i++)
#pragma unroll
        for (int j = 0; j < 4; j++) o[i][j] = 0.f;
    float m[4] = {-1e30f, -1e30f, -1e30f, -1e30f};
    float l[4] = {0.f, 0.f, 0.f, 0.f};

    for (int k0 = 0; k0 < Ll; k0 += 64) {
        __syncthreads();
        {
            int c = tid & 63, dg = tid >> 6;
#pragma unroll
            for (int s = 0; s < 4; s++) {
                int d0 = dg * 16 + s * 4;
                float4 a = *(const float4*)(kb + (size_t)(k0 + c) * Ff + d0);
                KPs[(d0 + 0) * 64 + c] = a.x;
                KPs[(d0 + 1) * 64 + c] = a.y;
                KPs[(d0 + 2) * 64 + c] = a.z;
                KPs[(d0 + 3) * 64 + c] = a.w;
            }
#pragma unroll
            for (int it = 0; it < 4; it++) {
                int f = tid + it * 256;
                int cc = f >> 4, d4 = (f & 15) << 2;
                *(float4*)(&Vs[cc * 64 + d4]) =
                    *(const float4*)(vb + (size_t)(k0 + cc) * Ff + d4);
            }
        }
        __syncthreads();

        float sc[4][4];
#pragma unroll
        for (int i = 0; i < 4; i++)
#pragma unroll
            for (int j = 0; j < 4; j++) sc[i][j] = 0.f;
#pragma unroll 8
        for (int d = 0; d < 64; d++) {
            float4 a  = *(const float4*)(&Qs[d * 64 + ty * 4]);
            float4 bq = *(const float4*)(&KPs[d * 64 + tx * 4]);
            float av[4]  = {a.x, a.y, a.z, a.w};
            float bvv[4] = {bq.x, bq.y, bq.z, bq.w};
#pragma unroll
            for (int i = 0; i < 4; i++)
#pragma unroll
                for (int j = 0; j < 4; j++) sc[i][j] += av[i] * bvv[j];
        }

#pragma unroll
        for (int i = 0; i < 4; i++) {
            float4 mv = *(const float4*)(mask + (size_t)(q0 + ty * 4 + i) * Ll + k0 + tx * 4);
            sc[i][0] += mv.x; sc[i][1] += mv.y; sc[i][2] += mv.z; sc[i][3] += mv.w;

            float mx = fmaxf(fmaxf(sc[i][0], sc[i][1]), fmaxf(sc[i][2], sc[i][3]));
#pragma unroll
            for (int off = 1; off < 16; off <<= 1)
                mx = fmaxf(mx, __shfl_xor_sync(0xffffffffu, mx, off));
            float newm = fmaxf(m[i], mx);
            float fac  = __expf(m[i] - newm);
            float sum  = 0.f;
#pragma unroll
            for (int j = 0; j < 4; j++) {
                float p = __expf(sc[i][j] - newm);
                sc[i][j] = p;
                sum += p;
            }
#pragma unroll
            for (int off = 1; off < 16; off <<= 1)
                sum += __shfl_xor_sync(0xffffffffu, sum, off);
            l[i] = l[i] * fac + sum;
            m[i] = newm;
#pragma unroll
            for (int j = 0; j < 4; j++) o[i][j] *= fac;
        }
        __syncthreads();

#pragma unroll
        for (int i = 0; i < 4; i++) {
            float4 pv = make_float4(sc[i][0], sc[i][1], sc[i][2], sc[i][3]);
            *(float4*)(&KPs[(ty * 4 + i) * 64 + tx * 4]) = pv;
        }
        __syncthreads();

#pragma unroll 4
        for (int c = 0; c < 64; c++) {
            float4 bv4 = *(const float4*)(&Vs[c * 64 + tx * 4]);
            float bvv[4] = {bv4.x, bv4.y, bv4.z, bv4.w};
#pragma unroll
            for (int i = 0; i < 4; i++) {
                float a = KPs[(ty * 4 + i) * 64 + c];
#pragma unroll
                for (int j = 0; j < 4; j++) o[i][j] += a * bvv[j];
            }
        }
    }

    // Normalize and write hi/lo fp16: O[b, q0+r, h*64 + d]
    const size_t obase = (size_t)b * Ll * Ff + h * Dd;
#pragma unroll
    for (int i = 0; i < 4; i++) {
        float inv = 1.0f / l[i];
        __half h0, h1, h2, h3, l0, l1, l2, l3;
        split1(o[i][0] * inv, h0, l0);
        split1(o[i][1] * inv, h1, l1);
        split1(o[i][2] * inv, h2, l2);
        split1(o[i][3] * inv, h3, l3);
        __half2 ha = __halves2half2(h0, h1), hb = __halves2half2(h2, h3);
        __half2 la = __halves2half2(l0, l1), lb = __halves2half2(l2, l3);
        uint2 hu, lu;
        hu.x = *(uint32_t*)&ha; hu.y = *(uint32_t*)&hb;
        lu.x = *(uint32_t*)&la; lu.y = *(uint32_t*)&lb;
        size_t idx = obase + (size_t)(q0 + ty * 4 + i) * Ff + tx * 4;
        *(uint2*)(Oh + idx) = hu;
        *(uint2*)(Ol + idx) = lu;
    }
}

// ---------------------------------------------------------------------------
// Launch
// ---------------------------------------------------------------------------
extern "C" void kernel_launch(void* const* d_in, const int* in_sizes, int n_in,
                              void* d_out, int out_size) {
    const float* kv    = (const float*)d_in[0];
    const float* q     = (const float*)d_in[1];
    const float* mask  = (const float*)d_in[2];
    const float* Wq    = (const float*)d_in[3];
    const float* Wk    = (const float*)d_in[4];
    const float* Wv    = (const float*)d_in[5];
    const float* Wo    = (const float*)d_in[6];
    const float* lnq_s = (const float*)d_in[7];
    const float* lnq_b = (const float*)d_in[8];
    const float* lnk_s = (const float*)d_in[9];
    const float* lnk_b = (const float*)d_in[10];
    const float* lnv_s = (const float*)d_in[11];
    const float* lnv_b = (const float*)d_in[12];
    float* out = (float*)d_out;

    float *pq, *pk, *pv;
    __half *pqh, *pql, *pkvh, *pkvl, *poh, *pol, *pwh, *pwl;
    cudaGetSymbolAddress((void**)&pq, g_q);
    cudaGetSymbolAddress((void**)&pk, g_k);
    cudaGetSymbolAddress((void**)&pv, g_v);
    cudaGetSymbolAddress((void**)&pqh, g_qh);
    cudaGetSymbolAddress((void**)&pql, g_ql);
    cudaGetSymbolAddress((void**)&pkvh, g_kvh);
    cudaGetSymbolAddress((void**)&pkvl, g_kvl);
    cudaGetSymbolAddress((void**)&poh, g_oh);
    cudaGetSymbolAddress((void**)&pol, g_ol);
    cudaGetSymbolAddress((void**)&pwh, g_wh);
    cudaGetSymbolAddress((void**)&pwl, g_wl);

    cudaFuncSetAttribute(gemm_mma, cudaFuncAttributeMaxDynamicSharedMemorySize,
                         GEMM_SMEM_BYTES);

    const int conv_blocks = (MTOT * Ff / 4) / 256;  // 8192
    dim3 gemm_grid(Ff / 128, MTOT / 128);           // (8, 64)

    // 0,1: split inputs to fp16 hi/lo
    convert_split<<<conv_blocks, 256>>>(q,  pqh,  pql);
    convert_split<<<conv_blocks, 256>>>(kv, pkvh, pkvl);
    // 2: transpose+split all weights
    transpose_split_all<<<dim3(32, 32, 4), dim3(32, 8)>>>(Wq, Wk, Wv, Wo);
    // 3,4,5: QKV projections (mma.sync fp16 split)
    gemm_mma<<<gemm_grid, 256, GEMM_SMEM_BYTES>>>(pqh,  pql,  pwh + 0 * (size_t)Ff * Ff, pwl + 0 * (size_t)Ff * Ff, pq);
    gemm_mma<<<gemm_grid, 256, GEMM_SMEM_BYTES>>>(pkvh, pkvl, pwh + 1 * (size_t)Ff * Ff, pwl + 1 * (size_t)Ff * Ff, pk);
    gemm_mma<<<gemm_grid, 256, GEMM_SMEM_BYTES>>>(pkvh, pkvl, pwh + 2 * (size_t)Ff * Ff, pwl + 2 * (size_t)Ff * Ff, pv);
    // 6,7,8: LayerNorms
    ln_kernel<<<MTOT, 256>>>(pq, lnq_s, lnq_b);
    ln_kernel<<<MTOT, 256>>>(pk, lnk_s, lnk_b);
    ln_kernel<<<MTOT, 256>>>(pv, lnv_s, lnv_b);
    // 9: attention (fp32), writes hi/lo fp16
    flash_kernel<<<dim3(Ll / 64, Bb * Hh), 256>>>(pq, pk, pv, mask, poh, pol);
    // 10: output projection
    gemm_mma<<<gemm_grid, 256, GEMM_SMEM_BYTES>>>(poh, pol, pwh + 3 * (size_t)Ff * Ff, pwl + 3 * (size_t)Ff * Ff, out);
}

// round 4
// speedup vs baseline: 2.3476x; 1.5048x over previous
#include <cuda_runtime.h>
#include <cuda_fp16.h>
#include <cstdint>
#include <math.h>

// Problem constants
#define Bb 8
#define Ll 1024
#define Ff 1024
#define Hh 16
#define Dd 64
#define MTOT (Bb * Ll)   // 8192
#define EPS 1e-6f

// ---------------------------------------------------------------------------
// Scratch (device globals: allocation-free rule)
// ---------------------------------------------------------------------------
__device__ float g_q[MTOT * Ff];
__device__ float g_k[MTOT * Ff];
__device__ float g_v[MTOT * Ff];
__device__ __half g_qh[MTOT * Ff];    // pre-GEMM q hi; reused as Q [B,H,L,D] hi
__device__ __half g_ql[MTOT * Ff];
__device__ __half g_kvh[MTOT * Ff];   // pre-GEMM kv hi; reused as K [B,H,L,D] hi
__device__ __half g_kvl[MTOT * Ff];
__device__ __half g_vth[MTOT * Ff];   // V^T [B,H,D,L] hi
__device__ __half g_vtl[MTOT * Ff];
__device__ __half g_oh[MTOT * Ff];    // attention out [B,L,F] hi
__device__ __half g_ol[MTOT * Ff];
__device__ __half g_wh[4][Ff * Ff];   // W^T hi  [N][K]
__device__ __half g_wl[4][Ff * Ff];   // W^T lo  [N][K]

// ---------------------------------------------------------------------------
// PTX helpers (all sm_80+ portable)
// ---------------------------------------------------------------------------
__device__ __forceinline__ uint32_t smem_u32(const void* p) {
    uint32_t a;
    asm("{ .reg .u64 t; cvta.to.shared.u64 t, %1; cvt.u32.u64 %0, t; }"
        : "=r"(a) : "l"(p));
    return a;
}

__device__ __forceinline__ void ldsm4(uint32_t* r, uint32_t addr) {
    asm volatile("ldmatrix.sync.aligned.m8n8.x4.shared.b16 {%0,%1,%2,%3}, [%4];"
                 : "=r"(r[0]), "=r"(r[1]), "=r"(r[2]), "=r"(r[3]) : "r"(addr));
}

__device__ __forceinline__ void mma16816(float* c, const uint32_t* a, const uint32_t* b) {
    asm volatile(
        "mma.sync.aligned.m16n8k16.row.col.f32.f16.f16.f32 "
        "{%0,%1,%2,%3}, {%4,%5,%6,%7}, {%8,%9}, {%0,%1,%2,%3};"
        : "+f"(c[0]), "+f"(c[1]), "+f"(c[2]), "+f"(c[3])
        : "r"(a[0]), "r"(a[1]), "r"(a[2]), "r"(a[3]), "r"(b[0]), "r"(b[1]));
}

#define CP_ASYNC16(dst, src) \
    asm volatile("cp.async.cg.shared.global [%0], [%1], 16;" :: "r"(dst), "l"(src) : "memory")
#define CP_COMMIT() asm volatile("cp.async.commit_group;" ::: "memory")
#define CP_WAIT1()  asm volatile("cp.async.wait_group 1;" ::: "memory")

__device__ __forceinline__ void split1(float v, __half& h, __half& l) {
    h = __float2half(v);
    l = __float2half(v - __half2float(h));
}

// ---------------------------------------------------------------------------
// fp32 -> (hi, lo) fp16 split, elementwise.
// ---------------------------------------------------------------------------
__global__ __launch_bounds__(256)
void convert_split(const float* __restrict__ X, __half* __restrict__ H,
                   __half* __restrict__ L) {
    int i = blockIdx.x * 256 + threadIdx.x;
    float4 v = ((const float4*)X)[i];
    __half h0, h1, h2, h3, l0, l1, l2, l3;
    split1(v.x, h0, l0); split1(v.y, h1, l1);
    split1(v.z, h2, l2); split1(v.w, h3, l3);
    __half2 ha = __halves2half2(h0, h1), hb = __halves2half2(h2, h3);
    __half2 la = __halves2half2(l0, l1), lb = __halves2half2(l2, l3);
    uint2 hu, lu;
    hu.x = *(uint32_t*)&ha; hu.y = *(uint32_t*)&hb;
    lu.x = *(uint32_t*)&la; lu.y = *(uint32_t*)&lb;
    ((uint2*)H)[i] = hu;
    ((uint2*)L)[i] = lu;
}

// ---------------------------------------------------------------------------
// Transpose + split all 4 weight matrices.
// ---------------------------------------------------------------------------
__global__ __launch_bounds__(256)
void transpose_split_all(const float* __restrict__ Wq, const float* __restrict__ Wk,
                         const float* __restrict__ Wv, const float* __restrict__ Wo) {
    __shared__ float t[32][33];
    const float* W;
    switch (blockIdx.z) {
        case 0: W = Wq; break;
        case 1: W = Wk; break;
        case 2: W = Wv; break;
        default: W = Wo; break;
    }
    __half* H = g_wh[blockIdx.z];
    __half* L = g_wl[blockIdx.z];

    const int tx = threadIdx.x, ty = threadIdx.y;
    const int x0 = blockIdx.x * 32;  // n
    const int y0 = blockIdx.y * 32;  // k
#pragma unroll
    for (int j = ty; j < 32; j += 8)
        t[j][tx] = W[(size_t)(y0 + j) * Ff + x0 + tx];
    __syncthreads();
#pragma unroll
    for (int j = ty; j < 32; j += 8) {
        float v = t[tx][j];
        __half h, l;
        split1(v, h, l);
        size_t idx = (size_t)(x0 + j) * Ff + y0 + tx;
        H[idx] = h;
        L[idx] = l;
    }
}

// ---------------------------------------------------------------------------
// mma.sync fp16 split-precision GEMM (unchanged from R3; 52% tensor pipe)
// ---------------------------------------------------------------------------
#define ROWST 40
#define MATST (128 * ROWST)
#define STAGEST (4 * MATST)
#define GEMM_SMEM_BYTES (2 * STAGEST * 2)

__device__ __forceinline__ void gemm_issue(
    const __half* __restrict__ Ah, const __half* __restrict__ Al,
    const __half* __restrict__ Bh, const __half* __restrict__ Bl,
    int m0, int n0, int kc, uint32_t sstage, int tid) {
    const int k0 = kc * 32;
    const int row = tid >> 2;
    const int ch  = tid & 3;
    const __half* srcs[4] = {Ah, Al, Bh, Bl};
#pragma unroll
    for (int j = 0; j < 8; j++) {
        const int mat = j >> 1;
        const int r = row + ((j & 1) << 6);
        const int gr = ((mat < 2) ? m0 : n0) + r;
        const __half* src = srcs[mat] + (size_t)gr * Ff + k0 + ch * 8;
        uint32_t dst = sstage + (uint32_t)(mat * MATST + r * ROWST + ch * 8) * 2;
        CP_ASYNC16(dst, src);
    }
}

__global__ __launch_bounds__(256)
void gemm_mma(const __half* __restrict__ Ah, const __half* __restrict__ Al,
              const __half* __restrict__ Bh, const __half* __restrict__ Bl,
              float* __restrict__ C) {
    extern __shared__ __align__(16) __half sm[];
    const int tid = threadIdx.x;
    const int lane = tid & 31;
    const int wid = tid >> 5;
    const int wm = (wid >> 2) * 64;
    const int wn = (wid & 3) * 32;
    const int m0 = blockIdx.y * 128;
    const int n0 = blockIdx.x * 128;
    const uint32_t sbase = smem_u32(sm);

    float acc[4][4][4];
#pragma unroll
    for (int i = 0; i < 4; i++)
#pragma unroll
        for (int j = 0; j < 4; j++)
#pragma unroll
            for (int r = 0; r < 4; r++) acc[i][j][r] = 0.f;

    gemm_issue(Ah, Al, Bh, Bl, m0, n0, 0, sbase, tid);
    CP_COMMIT();
    gemm_issue(Ah, Al, Bh, Bl, m0, n0, 1, sbase + STAGEST * 2, tid);
    CP_COMMIT();

    const int a_row = (lane & 15);
    const int a_col = (lane >> 4) << 3;
    const int bq = lane >> 3;
    const int b_row = (lane & 7) + ((bq >> 1) << 3);
    const int b_col = (bq & 1) << 3;

    for (int kc = 0; kc < 32; kc++) {
        CP_WAIT1();
        __syncthreads();
        const uint32_t st = sbase + (uint32_t)((kc & 1) * STAGEST) * 2;
        const uint32_t sAh = st;
        const uint32_t sAl = st + MATST * 2;
        const uint32_t sBh = st + 2 * MATST * 2;
        const uint32_t sBl = st + 3 * MATST * 2;

#pragma unroll
        for (int kk = 0; kk < 2; kk++) {
            uint32_t ah[4][4], al[4][4], bh[4][2], bl[4][2];
#pragma unroll
            for (int mi = 0; mi < 4; mi++) {
                uint32_t off = (uint32_t)((wm + mi * 16 + a_row) * ROWST + kk * 16 + a_col) * 2;
                ldsm4(ah[mi], sAh + off);
                ldsm4(al[mi], sAl + off);
            }
#pragma unroll
            for (int g = 0; g < 2; g++) {
                uint32_t off = (uint32_t)((wn + g * 16 + b_row) * ROWST + kk * 16 + b_col) * 2;
                uint32_t r[4];
                ldsm4(r, sBh + off);
                bh[g * 2][0] = r[0]; bh[g * 2][1] = r[1];
                bh[g * 2 + 1][0] = r[2]; bh[g * 2 + 1][1] = r[3];
                ldsm4(r, sBl + off);
                bl[g * 2][0] = r[0]; bl[g * 2][1] = r[1];
                bl[g * 2 + 1][0] = r[2]; bl[g * 2 + 1][1] = r[3];
            }
#pragma unroll
            for (int mi = 0; mi < 4; mi++)
#pragma unroll
                for (int ni = 0; ni < 4; ni++) {
                    mma16816(acc[mi][ni], ah[mi], bh[ni]);
                    mma16816(acc[mi][ni], ah[mi], bl[ni]);
                    mma16816(acc[mi][ni], al[mi], bh[ni]);
                }
        }
        __syncthreads();
        if (kc + 2 < 32)
            gemm_issue(Ah, Al, Bh, Bl, m0, n0, kc + 2,
                       sbase + (uint32_t)((kc & 1) * STAGEST) * 2, tid);
        CP_COMMIT();
    }

    const int er = lane >> 2;
    const int ec = (lane & 3) * 2;
#pragma unroll
    for (int mi = 0; mi < 4; mi++) {
        const int r0 = m0 + wm + mi * 16 + er;
#pragma unroll
        for (int ni = 0; ni < 4; ni++) {
            const int c = n0 + wn + ni * 8 + ec;
            *(float2*)(C + (size_t)r0 * Ff + c) = make_float2(acc[mi][ni][0], acc[mi][ni][1]);
            *(float2*)(C + (size_t)(r0 + 8) * Ff + c) = make_float2(acc[mi][ni][2], acc[mi][ni][3]);
        }
    }
}

// ---------------------------------------------------------------------------
// LayerNorm + reshape to [B,H,L,D] hi/lo fp16 (with optional scale, for Q).
// One block per row.
// ---------------------------------------------------------------------------
__global__ __launch_bounds__(256)
void ln_reshape(const float* __restrict__ x, const float* __restrict__ scale,
                const float* __restrict__ bias, float qscale,
                __half* __restrict__ OH, __half* __restrict__ OL) {
    __shared__ float red[16];
    const int row = blockIdx.x;         // b*1024 + l
    const int b = row >> 10, l = row & 1023;
    const int tid = threadIdx.x;
    const float* xr = x + (size_t)row * Ff;

    float4 v = *(const float4*)(xr + tid * 4);
    float s  = v.x + v.y + v.z + v.w;
    float sq = v.x * v.x + v.y * v.y + v.z * v.z + v.w * v.w;
#pragma unroll
    for (int o = 16; o > 0; o >>= 1) {
        s  += __shfl_xor_sync(0xffffffffu, s, o);
        sq += __shfl_xor_sync(0xffffffffu, sq, o);
    }
    const int warp = tid >> 5, lane = tid & 31;
    if (lane == 0) { red[warp] = s; red[warp + 8] = sq; }
    __syncthreads();
    float st = 0.f, sqt = 0.f;
#pragma unroll
    for (int w = 0; w < 8; w++) { st += red[w]; sqt += red[w + 8]; }

    const float mean = st * (1.0f / Ff);
    const float var  = sqt * (1.0f / Ff) - mean * mean;
    const float inv  = rsqrtf(var + EPS);

    float4 sc = *(const float4*)(scale + tid * 4);
    float4 bi = *(const float4*)(bias + tid * 4);
    float y0 = ((v.x - mean) * inv * sc.x + bi.x) * qscale;
    float y1 = ((v.y - mean) * inv * sc.y + bi.y) * qscale;
    float y2 = ((v.z - mean) * inv * sc.z + bi.z) * qscale;
    float y3 = ((v.w - mean) * inv * sc.w + bi.w) * qscale;

    const int col = tid * 4;
    const int h = col >> 6, d = col & 63;
    const size_t o = (((size_t)b * Hh + h) * Ll + l) * Dd + d;
    __half h0, h1, h2, h3, l0, l1, l2, l3;
    split1(y0, h0, l0); split1(y1, h1, l1);
    split1(y2, h2, l2); split1(y3, h3, l3);
    __half2 ha = __halves2half2(h0, h1), hb = __halves2half2(h2, h3);
    __half2 la = __halves2half2(l0, l1), lb = __halves2half2(l2, l3);
    uint2 hu, lu;
    hu.x = *(uint32_t*)&ha; hu.y = *(uint32_t*)&hb;
    lu.x = *(uint32_t*)&la; lu.y = *(uint32_t*)&lb;
    *(uint2*)(OH + o) = hu;
    *(uint2*)(OL + o) = lu;
}

// ---------------------------------------------------------------------------
// Row LayerNorm (in-place fp32) — still used for V before transpose.
// ---------------------------------------------------------------------------
__global__ __launch_bounds__(256)
void ln_kernel(float* __restrict__ x, const float* __restrict__ scale,
               const float* __restrict__ bias) {
    __shared__ float red[16];
    const int row = blockIdx.x;
    const int tid = threadIdx.x;
    float* xr = x + (size_t)row * Ff;

    float4 v = *(const float4*)(xr + tid * 4);
    float s  = v.x + v.y + v.z + v.w;
    float sq = v.x * v.x + v.y * v.y + v.z * v.z + v.w * v.w;
#pragma unroll
    for (int o = 16; o > 0; o >>= 1) {
        s  += __shfl_xor_sync(0xffffffffu, s, o);
        sq += __shfl_xor_sync(0xffffffffu, sq, o);
    }
    const int warp = tid >> 5, lane = tid & 31;
    if (lane == 0) { red[warp] = s; red[warp + 8] = sq; }
    __syncthreads();
    float st = 0.f, sqt = 0.f;
#pragma unroll
    for (int w = 0; w < 8; w++) { st += red[w]; sqt += red[w + 8]; }

    const float mean = st * (1.0f / Ff);
    const float var  = sqt * (1.0f / Ff) - mean * mean;
    const float inv  = rsqrtf(var + EPS);

    float4 sc = *(const float4*)(scale + tid * 4);
    float4 bi = *(const float4*)(bias + tid * 4);
    float4 out;
    out.x = (v.x - mean) * inv * sc.x + bi.x;
    out.y = (v.y - mean) * inv * sc.y + bi.y;
    out.z = (v.z - mean) * inv * sc.z + bi.z;
    out.w = (v.w - mean) * inv * sc.w + bi.w;
    *(float4*)(xr + tid * 4) = out;
}

// ---------------------------------------------------------------------------
// V transpose: fp32 [B,L,H*D] (post-LN) -> hi/lo fp16 [B,H,D,L].
// grid (B*H, L/64), 256 threads.
// ---------------------------------------------------------------------------
__global__ __launch_bounds__(256)
void v_transpose(const float* __restrict__ V, __half* __restrict__ TH,
                 __half* __restrict__ TL) {
    __shared__ float ts[64][65];
    const int bh = blockIdx.x;
    const int b = bh >> 4, h = bh & 15;
    const int l0 = blockIdx.y * 64;
    const int tid = threadIdx.x;
    {
        const int i = tid >> 2;
        const int c0 = (tid & 3) * 16;
        const float* src = V + ((size_t)b * Ll + l0 + i) * Ff + h * Dd + c0;
#pragma unroll
        for (int j = 0; j < 4; j++) {
            float4 a = *(const float4*)(src + j * 4);
            ts[i][c0 + j * 4 + 0] = a.x;
            ts[i][c0 + j * 4 + 1] = a.y;
            ts[i][c0 + j * 4 + 2] = a.z;
            ts[i][c0 + j * 4 + 3] = a.w;
        }
    }
    __syncthreads();
    {
        const int d = tid >> 2;
        const int lc = (tid & 3) * 16;
        const size_t o = ((size_t)bh * Dd + d) * Ll + l0 + lc;
        __align__(16) __half hs[16], ls[16];
#pragma unroll
        for (int j = 0; j < 16; j++) {
            float v = ts[lc + j][d];
            split1(v, hs[j], ls[j]);
        }
        *(uint4*)(TH + o)     = *(uint4*)(hs);
        *(uint4*)(TH + o + 8) = *(uint4*)(hs + 8);
        *(uint4*)(TL + o)     = *(uint4*)(ls);
        *(uint4*)(TL + o + 8) = *(uint4*)(ls + 8);
    }
}

// ---------------------------------------------------------------------------
// Flash attention with mma.sync (split fp16, 3 products both GEMMs).
// Grid (L/128, B*H), 256 threads = 8 warps; warp w owns q rows [w*16, w*16+16)
// over all 64 kv cols of a tile. No-max softmax (logits bounded ~|8| post-LN).
// Q layout [B,H,L,D] hi/lo (pre-scaled 0.125); K [B,H,L,D]; Vt [B,H,D,L].
// Output [B,L,F] hi/lo fp16.
// ---------------------------------------------------------------------------
#define FROWS 72
#define FTILE (64 * FROWS)              // halves per tile
#define FSTAGE (4 * FTILE)
#define FLASH_SMEM (2 * FSTAGE * 2)     // 73728 bytes

__device__ __forceinline__ void flash_issue(
    const __half* __restrict__ Kh, const __half* __restrict__ Kl,
    const __half* __restrict__ Vth, const __half* __restrict__ Vtl,
    int bh, int k0, uint32_t st, int tid) {
    const int row = tid >> 2;
    const int ch = tid & 3;
    const size_t kb = ((size_t)bh * Ll + k0) * Dd;
    const size_t vb = ((size_t)bh * Dd) * Ll + k0;
#pragma unroll
    for (int s = 0; s < 2; s++) {
        const int c8 = ch + s * 4;
        const uint32_t so = (uint32_t)(row * FROWS + c8 * 8) * 2;
        CP_ASYNC16(st + 0 * FTILE * 2 + so, Kh + kb + (size_t)row * Dd + c8 * 8);
        CP_ASYNC16(st + 1 * FTILE * 2 + so, Kl + kb + (size_t)row * Dd + c8 * 8);
        CP_ASYNC16(st + 2 * FTILE * 2 + so, Vth + vb + (size_t)row * Ll + c8 * 8);
        CP_ASYNC16(st + 3 * FTILE * 2 + so, Vtl + vb + (size_t)row * Ll + c8 * 8);
    }
}

__global__ __launch_bounds__(256)
void flash_mma(const __half* __restrict__ Qh, const __half* __restrict__ Ql,
               const __half* __restrict__ Kh, const __half* __restrict__ Kl,
               const __half* __restrict__ Vth, const __half* __restrict__ Vtl,
               const float* __restrict__ mask,
               __half* __restrict__ Oh, __half* __restrict__ Ol) {
    extern __shared__ __align__(16) __half fsm[];
    const int tid = threadIdx.x;
    const int lane = tid & 31;
    const int wid = tid >> 5;
    const int q0 = blockIdx.x * 128;
    const int bh = blockIdx.y;
    const int b = bh >> 4, h = bh & 15;
    const uint32_t sbase = smem_u32(fsm);
    const int wr0 = q0 + wid * 16;
    const int er = lane >> 2;
    const int ec = (lane & 3) * 2;

    // Q fragments (loop-invariant), rows wr0+er(+8), cols kk*16 + ec(+8)
    uint32_t qfh[4][4], qfl[4][4];
    {
        const size_t qb = (size_t)bh * Ll * Dd;
        const size_t r0 = qb + (size_t)(wr0 + er) * Dd;
        const size_t r1 = qb + (size_t)(wr0 + er + 8) * Dd;
#pragma unroll
        for (int kk = 0; kk < 4; kk++) {
            const int c0 = kk * 16 + ec, c1 = kk * 16 + ec + 8;
            qfh[kk][0] = *(const uint32_t*)(Qh + r0 + c0);
            qfh[kk][1] = *(const uint32_t*)(Qh + r1 + c0);
            qfh[kk][2] = *(const uint32_t*)(Qh + r0 + c1);
            qfh[kk][3] = *(const uint32_t*)(Qh + r1 + c1);
            qfl[kk][0] = *(const uint32_t*)(Ql + r0 + c0);
            qfl[kk][1] = *(const uint32_t*)(Ql + r1 + c0);
            qfl[kk][2] = *(const uint32_t*)(Ql + r0 + c1);
            qfl[kk][3] = *(const uint32_t*)(Ql + r1 + c1);
        }
    }

    float oacc[8][4];
#pragma unroll
    for (int i = 0; i < 8; i++)
#pragma unroll
        for (int j = 0; j < 4; j++) oacc[i][j] = 0.f;
    float lsum0 = 0.f, lsum1 = 0.f;

    flash_issue(Kh, Kl, Vth, Vtl, bh, 0, sbase, tid);
    CP_COMMIT();
    flash_issue(Kh, Kl, Vth, Vtl, bh, 64, sbase + FSTAGE * 2, tid);
    CP_COMMIT();

    const int bq = lane >> 3;
    const int b_row = (lane & 7) + ((bq >> 1) << 3);
    const int b_col = (bq & 1) << 3;

    for (int t = 0; t < 16; t++) {
        CP_WAIT1();
        __syncthreads();
        const uint32_t st = sbase + (uint32_t)((t & 1) * FSTAGE) * 2;
        const uint32_t sKh = st;
        const uint32_t sKl = st + FTILE * 2;
        const uint32_t sVh = st + 2 * FTILE * 2;
        const uint32_t sVl = st + 3 * FTILE * 2;

        // S = Qs @ K^T  (fragments over 8 n8-tiles)
        float sc[8][4];
#pragma unroll
        for (int i = 0; i < 8; i++)
#pragma unroll
            for (int j = 0; j < 4; j++) sc[i][j] = 0.f;

#pragma unroll
        for (int kk = 0; kk < 4; kk++) {
#pragma unroll
            for (int g = 0; g < 4; g++) {
                const uint32_t off = (uint32_t)((g * 16 + b_row) * FROWS + kk * 16 + b_col) * 2;
                uint32_t rh[4], rl[4];
                ldsm4(rh, sKh + off);
                ldsm4(rl, sKl + off);
#pragma unroll
                for (int u = 0; u < 2; u++) {
                    const int ni = 2 * g + u;
                    uint32_t bh2[2] = {rh[2 * u], rh[2 * u + 1]};
                    uint32_t bl2[2] = {rl[2 * u], rl[2 * u + 1]};
                    mma16816(sc[ni], qfh[kk], bh2);
                    mma16816(sc[ni], qfh[kk], bl2);
                    mma16816(sc[ni], qfl[kk], bh2);
                }
            }
        }

        // mask + exp + rowsum + convert P to A-fragments (hi/lo)
        const int k0 = t * 64;
        uint32_t pah[4][4], pal[4][4];
        const float* mr0 = mask + (size_t)(wr0 + er) * Ll + k0 + ec;
        const float* mr1 = mr0 + 8 * Ll;
#pragma unroll
        for (int ni = 0; ni < 8; ni++) {
            float2 m0 = *(const float2*)(mr0 + ni * 8);
            float2 m1 = *(const float2*)(mr1 + ni * 8);
            float p0 = __expf(sc[ni][0] + m0.x);
            float p1 = __expf(sc[ni][1] + m0.y);
            float p2 = __expf(sc[ni][2] + m1.x);
            float p3 = __expf(sc[ni][3] + m1.y);
            lsum0 += p0 + p1;
            lsum1 += p2 + p3;
            __half2 h01 = __floats2half2_rn(p0, p1);
            __half2 h23 = __floats2half2_rn(p2, p3);
            float2 f01 = __half22float2(h01);
            float2 f23 = __half22float2(h23);
            __half2 l01 = __floats2half2_rn(p0 - f01.x, p1 - f01.y);
            __half2 l23 = __floats2half2_rn(p2 - f23.x, p3 - f23.y);
            const int kc = ni >> 1, u = ni & 1;
            pah[kc][u * 2 + 0] = *(uint32_t*)&h01;
            pah[kc][u * 2 + 1] = *(uint32_t*)&h23;
            pal[kc][u * 2 + 0] = *(uint32_t*)&l01;
            pal[kc][u * 2 + 1] = *(uint32_t*)&l23;
        }

        // O += P @ V  (Vt tile is [d][kv])
#pragma unroll
        for (int kc = 0; kc < 4; kc++) {
#pragma unroll
            for (int g = 0; g < 4; g++) {
                const uint32_t off = (uint32_t)((g * 16 + b_row) * FROWS + kc * 16 + b_col) * 2;
                uint32_t rh[4], rl[4];
                ldsm4(rh, sVh + off);
                ldsm4(rl, sVl + off);
#pragma unroll
                for (int u = 0; u < 2; u++) {
                    const int ni = 2 * g + u;
                    uint32_t bh2[2] = {rh[2 * u], rh[2 * u + 1]};
                    uint32_t bl2[2] = {rl[2 * u], rl[2 * u + 1]};
                    mma16816(oacc[ni], pah[kc], bh2);
                    mma16816(oacc[ni], pah[kc], bl2);
                    mma16816(oacc[ni], pal[kc], bh2);
                }
            }
        }
        __syncthreads();
        if (t + 2 < 16)
            flash_issue(Kh, Kl, Vth, Vtl, bh, (t + 2) * 64,
                        sbase + (uint32_t)((t & 1) * FSTAGE) * 2, tid);
        CP_COMMIT();
    }

    // row sums across the quad (lanes sharing er)
    lsum0 += __shfl_xor_sync(0xffffffffu, lsum0, 1);
    lsum0 += __shfl_xor_sync(0xffffffffu, lsum0, 2);
    lsum1 += __shfl_xor_sync(0xffffffffu, lsum1, 1);
    lsum1 += __shfl_xor_sync(0xffffffffu, lsum1, 2);
    const float inv0 = 1.0f / lsum0;
    const float inv1 = 1.0f / lsum1;

    // write O hi/lo: rows wr0+er(+8), cols h*64 + ni*8 + ec
    const size_t ob0 = ((size_t)b * Ll + wr0 + er) * Ff + h * Dd + ec;
    const size_t ob1 = ob0 + (size_t)8 * Ff;
#pragma unroll
    for (int ni = 0; ni < 8; ni++) {
        float o0 = oacc[ni][0] * inv0, o1 = oacc[ni][1] * inv0;
        float o2 = oacc[ni][2] * inv1, o3 = oacc[ni][3] * inv1;
        __half2 h01 = __floats2half2_rn(o0, o1);
        __half2 h23 = __floats2half2_rn(o2, o3);
        float2 f01 = __half22float2(h01);
        float2 f23 = __half22float2(h23);
        __half2 l01 = __floats2half2_rn(o0 - f01.x, o1 - f01.y);
        __half2 l23 = __floats2half2_rn(o2 - f23.x, o3 - f23.y);
        *(uint32_t*)(Oh + ob0 + ni * 8) = *(uint32_t*)&h01;
        *(uint32_t*)(Oh + ob1 + ni * 8) = *(uint32_t*)&h23;
        *(uint32_t*)(Ol + ob0 + ni * 8) = *(uint32_t*)&l01;
        *(uint32_t*)(Ol + ob1 + ni * 8) = *(uint32_t*)&l23;
    }
}

// ---------------------------------------------------------------------------
// Launch
// ---------------------------------------------------------------------------
extern "C" void kernel_launch(void* const* d_in, const int* in_sizes, int n_in,
                              void* d_out, int out_size) {
    const float* kv    = (const float*)d_in[0];
    const float* q     = (const float*)d_in[1];
    const float* mask  = (const float*)d_in[2];
    const float* Wq    = (const float*)d_in[3];
    const float* Wk    = (const float*)d_in[4];
    const float* Wv    = (const float*)d_in[5];
    const float* Wo    = (const float*)d_in[6];
    const float* lnq_s = (const float*)d_in[7];
    const float* lnq_b = (const float*)d_in[8];
    const float* lnk_s = (const float*)d_in[9];
    const float* lnk_b = (const float*)d_in[10];
    const float* lnv_s = (const float*)d_in[11];
    const float* lnv_b = (const float*)d_in[12];
    float* out = (float*)d_out;

    float *pq, *pk, *pv;
    __half *pqh, *pql, *pkvh, *pkvl, *pvth, *pvtl, *poh, *pol, *pwh, *pwl;
    cudaGetSymbolAddress((void**)&pq, g_q);
    cudaGetSymbolAddress((void**)&pk, g_k);
    cudaGetSymbolAddress((void**)&pv, g_v);
    cudaGetSymbolAddress((void**)&pqh, g_qh);
    cudaGetSymbolAddress((void**)&pql, g_ql);
    cudaGetSymbolAddress((void**)&pkvh, g_kvh);
    cudaGetSymbolAddress((void**)&pkvl, g_kvl);
    cudaGetSymbolAddress((void**)&pvth, g_vth);
    cudaGetSymbolAddress((void**)&pvtl, g_vtl);
    cudaGetSymbolAddress((void**)&poh, g_oh);
    cudaGetSymbolAddress((void**)&pol, g_ol);
    cudaGetSymbolAddress((void**)&pwh, g_wh);
    cudaGetSymbolAddress((void**)&pwl, g_wl);

    cudaFuncSetAttribute(gemm_mma, cudaFuncAttributeMaxDynamicSharedMemorySize,
                         GEMM_SMEM_BYTES);
    cudaFuncSetAttribute(flash_mma, cudaFuncAttributeMaxDynamicSharedMemorySize,
                         FLASH_SMEM);

    const int conv_blocks = (MTOT * Ff / 4) / 256;  // 8192
    dim3 gemm_grid(Ff / 128, MTOT / 128);           // (8, 64)

    // split inputs to fp16 hi/lo for projections
    convert_split<<<conv_blocks, 256>>>(q,  pqh,  pql);
    convert_split<<<conv_blocks, 256>>>(kv, pkvh, pkvl);
    transpose_split_all<<<dim3(32, 32, 4), dim3(32, 8)>>>(Wq, Wk, Wv, Wo);
    // QKV projections
    gemm_mma<<<gemm_grid, 256, GEMM_SMEM_BYTES>>>(pqh,  pql,  pwh + 0 * (size_t)Ff * Ff, pwl + 0 * (size_t)Ff * Ff, pq);
    gemm_mma<<<gemm_grid, 256, GEMM_SMEM_BYTES>>>(pkvh, pkvl, pwh + 1 * (size_t)Ff * Ff, pwl + 1 * (size_t)Ff * Ff, pk);
    gemm_mma<<<gemm_grid, 256, GEMM_SMEM_BYTES>>>(pkvh, pkvl, pwh + 2 * (size_t)Ff * Ff, pwl + 2 * (size_t)Ff * Ff, pv);
    // LN + reshape for Q (x0.125) and K; LN + transpose for V
    ln_reshape<<<MTOT, 256>>>(pq, lnq_s, lnq_b, 0.125f, pqh, pql);
    ln_reshape<<<MTOT, 256>>>(pk, lnk_s, lnk_b, 1.0f, pkvh, pkvl);
    ln_kernel<<<MTOT, 256>>>(pv, lnv_s, lnv_b);
    v_transpose<<<dim3(Bb * Hh, Ll / 64), 256>>>(pv, pvth, pvtl);
    // attention (tensor cores)
    flash_mma<<<dim3(Ll / 128, Bb * Hh), 256, FLASH_SMEM>>>(
        pqh, pql, pkvh, pkvl, pvth, pvtl, mask, poh, pol);
    // output projection
    gemm_mma<<<gemm_grid, 256, GEMM_SMEM_BYTES>>>(poh, pol, pwh + 3 * (size_t)Ff * Ff, pwl + 3 * (size_t)Ff * Ff, out);
}